// round 2
// baseline (speedup 1.0000x reference)
#include <cuda_runtime.h>
#include <cuda_bf16.h>
#include <stdint.h>

// Problem shape (fixed by dataset reference)
#define N_ROWS 8192
#define DIM    1024
#define TM     128
#define TN     128
#define KC     64                      // K elems per chunk (64 bf16 = 128B row)
#define CHUNKS (DIM / KC)              // 16
#define TILE_BYTES (TM * 128)          // 16384: 128 rows x 128 bytes, swizzled
#define S      3                       // pipeline stages
#define MTILES (N_ROWS / TM)           // 64
#define NTILES (N_ROWS / TN)           // 64

// Static device scratch (runtime allocation is forbidden)
__device__ __align__(1024) uint8_t g_A[(size_t)MTILES * CHUNKS * TILE_BYTES]; // 16 MB
__device__ __align__(1024) uint8_t g_B[(size_t)NTILES * CHUNKS * TILE_BYTES]; // 16 MB
__device__ float g_rowloss[N_ROWS];
__device__ int   g_haspos[N_ROWS];

// ------------------------- PTX helpers (base sm_103 ISA only!) ----------
__device__ __forceinline__ uint32_t smem_u32(const void* p) {
    uint32_t a;
    asm("{ .reg .u64 t; cvta.to.shared.u64 t, %1; cvt.u32.u64 %0, t; }" : "=r"(a) : "l"(p));
    return a;
}

#define MBAR_INIT(addr, cnt) \
    asm volatile("mbarrier.init.shared.b64 [%0], %1;" :: "r"(addr), "r"(cnt) : "memory")
#define MBAR_EXPECT_TX(addr, bytes) \
    asm volatile("mbarrier.arrive.expect_tx.shared.b64 _, [%0], %1;" :: "r"(addr), "r"(bytes) : "memory")
#define MBAR_ARRIVE(addr) \
    asm volatile("mbarrier.arrive.shared.b64 _, [%0];" :: "r"(addr) : "memory")

__device__ __forceinline__ void mbar_wait(uint32_t mbar, uint32_t parity) {
    asm volatile(
        "{\n\t.reg .pred P;\n\t"
        "WAIT_%=:\n\t"
        "mbarrier.try_wait.parity.acquire.cta.shared::cta.b64 P, [%0], %1, 0x989680;\n\t"
        "@P bra.uni DONE_%=;\n\t"
        "bra.uni WAIT_%=;\n\t"
        "DONE_%=:\n\t}"
        :: "r"(mbar), "r"(parity) : "memory");
}

// Plain (non-tensor) 1-D bulk copy: 16 KB contiguous, pre-swizzled in GMEM.
__device__ __forceinline__ void bulk_g2s(uint32_t dst, const void* src, uint32_t bytes, uint32_t mbar) {
    asm volatile(
        "cp.async.bulk.shared::cta.global.mbarrier::complete_tx::bytes [%0], [%1], %2, [%3];"
        :: "r"(dst), "l"(src), "r"(bytes), "r"(mbar) : "memory");
}

__device__ __forceinline__ void ldm_x4(uint32_t (&r)[4], uint32_t addr) {
    asm volatile("ldmatrix.sync.aligned.m8n8.x4.shared.b16 {%0,%1,%2,%3}, [%4];"
                 : "=r"(r[0]), "=r"(r[1]), "=r"(r[2]), "=r"(r[3]) : "r"(addr));
}

__device__ __forceinline__ void mma_bf16(float* c, const uint32_t* a, uint32_t b0, uint32_t b1) {
    asm volatile(
        "mma.sync.aligned.m16n8k16.row.col.f32.bf16.bf16.f32 "
        "{%0,%1,%2,%3}, {%4,%5,%6,%7}, {%8,%9}, {%0,%1,%2,%3};"
        : "+f"(c[0]), "+f"(c[1]), "+f"(c[2]), "+f"(c[3])
        : "r"(a[0]), "r"(a[1]), "r"(a[2]), "r"(a[3]), "r"(b0), "r"(b1));
}

// ------------------------- kernels -------------------------

__global__ void zero_kernel() {
    int i = blockIdx.x * blockDim.x + threadIdx.x;
    if (i < N_ROWS) { g_rowloss[i] = 0.0f; g_haspos[i] = 0; }
}

// One block per row. L2-normalize in fp32, emit bf16 into the pre-swizzled,
// tile-contiguous layout that the GEMM bulk-copies verbatim into SMEM.
// Swizzle: byte ^ ((byte>>3)&0x70)  (SW128-style, matches ldmatrix readers)
__global__ void __launch_bounds__(128) normalize_kernel(const float* __restrict__ in, int which) {
    uint8_t* dst = which ? g_B : g_A;
    const int r = blockIdx.x;
    const int t = threadIdx.x;
    const float4* row = reinterpret_cast<const float4*>(in + (size_t)r * DIM);
    float4 v0 = row[t * 2];
    float4 v1 = row[t * 2 + 1];

    float ss = v0.x * v0.x + v0.y * v0.y + v0.z * v0.z + v0.w * v0.w
             + v1.x * v1.x + v1.y * v1.y + v1.z * v1.z + v1.w * v1.w;
    #pragma unroll
    for (int o = 16; o > 0; o >>= 1) ss += __shfl_xor_sync(0xFFFFFFFFu, ss, o);
    __shared__ float wsum[4];
    if ((t & 31) == 0) wsum[t >> 5] = ss;
    __syncthreads();
    float tot = wsum[0] + wsum[1] + wsum[2] + wsum[3];
    float inv = rsqrtf(tot + 1e-12f);

    uint32_t p[4];
    __nv_bfloat162 b;
    b = __floats2bfloat162_rn(v0.x * inv, v0.y * inv); p[0] = *reinterpret_cast<uint32_t*>(&b);
    b = __floats2bfloat162_rn(v0.z * inv, v0.w * inv); p[1] = *reinterpret_cast<uint32_t*>(&b);
    b = __floats2bfloat162_rn(v1.x * inv, v1.y * inv); p[2] = *reinterpret_cast<uint32_t*>(&b);
    b = __floats2bfloat162_rn(v1.z * inv, v1.w * inv); p[3] = *reinterpret_cast<uint32_t*>(&b);

    const int k0 = t * 8;                                     // element offset in K
    size_t tile = ((size_t)(r >> 7) * CHUNKS + (k0 >> 6)) * TILE_BYTES;
    uint32_t byte = (uint32_t)(r & 127) * 128 + (uint32_t)(k0 & 63) * 2;
    byte ^= (byte >> 3) & 0x70;                               // swizzle
    *reinterpret_cast<uint4*>(dst + tile + byte) = make_uint4(p[0], p[1], p[2], p[3]);
}

// GEMM + fused masked-loss epilogue.
// 256 threads = 8 warps, 4(M) x 2(N); each warp computes 32x64 via mma.sync.
// smem map: [0..24) full[3], [32..56) empty[3], [128..640) target_row tile,
//           [1024..) 3 stages of (A 16K + B 16K)
#define SMEM_STAGE_BYTES (2 * TILE_BYTES)
#define SMEM_TOTAL (1024 + S * SMEM_STAGE_BYTES)

__global__ void __launch_bounds__(256, 2) gemm_kernel(const int* __restrict__ targets_col,
                                                      const int* __restrict__ target_row) {
    extern __shared__ uint8_t smem[];
    const uint32_t sb = smem_u32(smem);
    const int tid = threadIdx.x;
    const int wid = tid >> 5;
    const int l   = tid & 31;
    const int wm  = wid & 3;        // M warp index (0..3)
    const int wn  = wid >> 2;       // N warp index (0..1)
    const int mTile = blockIdx.x;
    const int nTile = blockIdx.y;

    int* s_tr = reinterpret_cast<int*>(smem + 128);

    if (tid == 0) {
        #pragma unroll
        for (int s = 0; s < S; s++) {
            MBAR_INIT(sb + 0  + 8 * s, 1);   // full: single expect_tx arrive
            MBAR_INIT(sb + 32 + 8 * s, 8);   // empty: one arrive per warp
        }
    }
    if (tid < TN) s_tr[tid] = target_row[nTile * TN + tid];
    __syncthreads();

    const uint8_t* srcA = g_A + (size_t)mTile * CHUNKS * TILE_BYTES;
    const uint8_t* srcB = g_B + (size_t)nTile * CHUNKS * TILE_BYTES;

    // Prologue: issue chunks 0..S-2
    if (tid == 0) {
        #pragma unroll
        for (int nc = 0; nc < S - 1; nc++) {
            MBAR_EXPECT_TX(sb + 8 * nc, 2 * TILE_BYTES);
            const uint32_t dst = sb + 1024 + nc * SMEM_STAGE_BYTES;
            bulk_g2s(dst,              srcA + (size_t)nc * TILE_BYTES, TILE_BYTES, sb + 8 * nc);
            bulk_g2s(dst + TILE_BYTES, srcB + (size_t)nc * TILE_BYTES, TILE_BYTES, sb + 8 * nc);
        }
    }

    // Per-lane constant address parts. Swizzle simplifies to
    // addr = row*128 + (colByte ^ ((row&7)*16)) since colByte < 128.
    uint32_t aRow[2], aXor[2];
    #pragma unroll
    for (int bm = 0; bm < 2; bm++) {
        const int r = wm * 32 + bm * 16 + (l & 15);
        aRow[bm] = (uint32_t)r * 128;
        aXor[bm] = (uint32_t)(r & 7) * 16;
    }
    const uint32_t aColHi = (uint32_t)(l >> 4) * 16;
    uint32_t bRow[4], bXor[4];
    #pragma unroll
    for (int g = 0; g < 4; g++) {
        const int r = wn * 64 + g * 16 + ((l >> 4) * 8) + (l & 7);
        bRow[g] = (uint32_t)r * 128;
        bXor[g] = (uint32_t)(r & 7) * 16;
    }
    const uint32_t bColHi = (uint32_t)((l >> 3) & 1) * 16;

    float acc[2][8][4];
    #pragma unroll
    for (int bm = 0; bm < 2; bm++)
        #pragma unroll
        for (int bn = 0; bn < 8; bn++)
            #pragma unroll
            for (int i = 0; i < 4; i++) acc[bm][bn][i] = 0.0f;

    for (int c = 0; c < CHUNKS; c++) {
        const int s = c % S;
        // Producer: issue chunk c+S-1 into its stage
        if (tid == 0) {
            const int nc = c + S - 1;
            if (nc < CHUNKS) {
                const int ns = nc % S;
                if (nc >= S) mbar_wait(sb + 32 + 8 * ns, ((nc - S) / S) & 1);
                MBAR_EXPECT_TX(sb + 8 * ns, 2 * TILE_BYTES);
                const uint32_t dst = sb + 1024 + ns * SMEM_STAGE_BYTES;
                bulk_g2s(dst,              srcA + (size_t)nc * TILE_BYTES, TILE_BYTES, sb + 8 * ns);
                bulk_g2s(dst + TILE_BYTES, srcB + (size_t)nc * TILE_BYTES, TILE_BYTES, sb + 8 * ns);
            }
        }
        mbar_wait(sb + 8 * s, (c / S) & 1);

        const uint32_t stA = sb + 1024 + s * SMEM_STAGE_BYTES;
        const uint32_t stB = stA + TILE_BYTES;
        #pragma unroll
        for (int ks = 0; ks < 4; ks++) {
            const uint32_t kb = ks * 32;
            uint32_t a[2][4];
            #pragma unroll
            for (int bm = 0; bm < 2; bm++)
                ldm_x4(a[bm], stA + aRow[bm] + ((kb + aColHi) ^ aXor[bm]));
            #pragma unroll
            for (int g = 0; g < 4; g++) {
                uint32_t b[4];
                ldm_x4(b, stB + bRow[g] + ((kb + bColHi) ^ bXor[g]));
                #pragma unroll
                for (int bm = 0; bm < 2; bm++) {
                    mma_bf16(acc[bm][2 * g],     a[bm], b[0], b[1]);
                    mma_bf16(acc[bm][2 * g + 1], a[bm], b[2], b[3]);
                }
            }
        }
        if (l == 0) MBAR_ARRIVE(sb + 32 + 8 * s);
    }

    // ---- fused masked-loss epilogue (register-resident sim values) ----
    // acc element (bm, bn, i): row = wm*32 + bm*16 + (l>>2) + (i>=2 ? 8 : 0)
    //                          col = wn*64 + bn*8 + (l&3)*2 + (i&1)
    const int gmBase = mTile * TM + wm * 32 + (l >> 2);
    int tcv[4];
    #pragma unroll
    for (int r = 0; r < 4; r++) {
        const int off = (r >> 1) * 16 + (r & 1) * 8;   // rowIdx = bm*2 + hi
        tcv[r] = targets_col[gmBase + off];
    }
    float part[4] = {0.f, 0.f, 0.f, 0.f};
    int flag[4] = {0, 0, 0, 0};
    #pragma unroll
    for (int bm = 0; bm < 2; bm++)
        #pragma unroll
        for (int bn = 0; bn < 8; bn++)
            #pragma unroll
            for (int i = 0; i < 4; i++) {
                const float sim = acc[bm][bn][i];
                const int ridx = bm * 2 + (i >> 1);
                const int ncol = wn * 64 + bn * 8 + (l & 3) * 2 + (i & 1);
                if (tcv[ridx] == s_tr[ncol]) {
                    if (sim < 0.99999f) { part[ridx] += 1.0f - sim; flag[ridx] = 1; }
                } else if (sim > 0.5f) {
                    part[ridx] += sim;
                }
            }
    // lanes 4g..4g+3 share the same 4 rows -> reduce across them
    #pragma unroll
    for (int r = 0; r < 4; r++) {
        part[r] += __shfl_xor_sync(0xFFFFFFFFu, part[r], 1);
        part[r] += __shfl_xor_sync(0xFFFFFFFFu, part[r], 2);
        flag[r] |= __shfl_xor_sync(0xFFFFFFFFu, flag[r], 1);
        flag[r] |= __shfl_xor_sync(0xFFFFFFFFu, flag[r], 2);
    }
    if ((l & 3) == 0) {
        #pragma unroll
        for (int r = 0; r < 4; r++) {
            const int gm = gmBase + (r >> 1) * 16 + (r & 1) * 8;
            atomicAdd(&g_rowloss[gm], part[r]);
            if (flag[r]) g_haspos[gm] = 1;     // idempotent; races benign
        }
    }
}

__global__ void __launch_bounds__(1024) final_kernel(float* __restrict__ out) {
    __shared__ float s[1024];
    const int t = threadIdx.x;
    float sum = 0.0f;
    #pragma unroll
    for (int i = t; i < N_ROWS; i += 1024)
        sum += g_haspos[i] ? g_rowloss[i] : 0.0f;
    s[t] = sum;
    __syncthreads();
    #pragma unroll
    for (int o = 512; o > 0; o >>= 1) {
        if (t < o) s[t] += s[t + o];
        __syncthreads();
    }
    if (t == 0) out[0] = s[0] / (float)N_ROWS;
}

// ------------------------- launch -------------------------
extern "C" void kernel_launch(void* const* d_in, const int* in_sizes, int n_in,
                              void* d_out, int out_size) {
    const float* inputs_col  = (const float*)d_in[0];
    const int*   targets_col = (const int*)d_in[1];
    const float* inputs_row  = (const float*)d_in[2];
    const int*   target_row  = (const int*)d_in[3];
    (void)in_sizes; (void)n_in; (void)out_size;

    cudaFuncSetAttribute(gemm_kernel, cudaFuncAttributeMaxDynamicSharedMemorySize, SMEM_TOTAL);

    zero_kernel<<<(N_ROWS + 255) / 256, 256>>>();
    normalize_kernel<<<N_ROWS, 128>>>(inputs_col, 0);
    normalize_kernel<<<N_ROWS, 128>>>(inputs_row, 1);
    dim3 grid(MTILES, NTILES);
    gemm_kernel<<<grid, 256, SMEM_TOTAL>>>(targets_col, target_row);
    final_kernel<<<1, 1024>>>((float*)d_out);
}